// round 15
// baseline (speedup 1.0000x reference)
#include <cuda_runtime.h>
#include <cuda_bf16.h>
#include <cstdint>
#include <cstddef>

#define Bn  4
#define NHn 8
#define Cn  32
#define Hn  128
#define Wn  128
#define HWn (Hn*Wn)
#define CDn 256

// ---------------- scratch (device globals) ----------------
__device__ __align__(16) float g_qp [Bn*HWn*Cn];
__device__ __align__(16) float g_pc [Bn*HWn*Cn];
__device__ __align__(16) float g_xi [Bn*NHn*HWn*Cn];
__device__ __align__(16) float g_cat[(size_t)Bn*NHn*HWn*96];

// ---------------- helpers ----------------
__device__ __forceinline__ float4 f4fma(float a, float4 w, float4 acc) {
    acc.x = fmaf(a, w.x, acc.x); acc.y = fmaf(a, w.y, acc.y);
    acc.z = fmaf(a, w.z, acc.z); acc.w = fmaf(a, w.w, acc.w);
    return acc;
}
__device__ __forceinline__ uint32_t smem_u32(const void* p) {
    uint32_t a;
    asm("{ .reg .u64 t; cvta.to.shared.u64 t, %1; cvt.u32.u64 %0, t; }" : "=r"(a) : "l"(p));
    return a;
}
__device__ __forceinline__ void ldm4(uint32_t* r, uint32_t addr) {
    asm volatile("ldmatrix.sync.aligned.m8n8.x4.shared.b16 {%0,%1,%2,%3}, [%4];"
        : "=r"(r[0]), "=r"(r[1]), "=r"(r[2]), "=r"(r[3]) : "r"(addr));
}
__device__ __forceinline__ void mma4(float* d, const uint32_t* a, uint32_t b0, uint32_t b1) {
    asm volatile(
        "mma.sync.aligned.m16n8k16.row.col.f32.bf16.bf16.f32 "
        "{%0,%1,%2,%3}, {%4,%5,%6,%7}, {%8,%9}, {%0,%1,%2,%3};"
        : "+f"(d[0]), "+f"(d[1]), "+f"(d[2]), "+f"(d[3])
        : "r"(a[0]), "r"(a[1]), "r"(a[2]), "r"(a[3]), "r"(b0), "r"(b1));
}
__device__ __forceinline__ void packhl(const float* x, uint32_t* hq, uint32_t* lq, int n2) {
    #pragma unroll
    for (int i = 0; i < n2; i++) {
        __nv_bfloat16 h0 = __float2bfloat16(x[2*i]),   h1 = __float2bfloat16(x[2*i+1]);
        __nv_bfloat16 l0 = __float2bfloat16(x[2*i]   - __bfloat162float(h0));
        __nv_bfloat16 l1 = __float2bfloat16(x[2*i+1] - __bfloat162float(h1));
        hq[i] = (uint32_t)__bfloat16_as_ushort(h0) | ((uint32_t)__bfloat16_as_ushort(h1) << 16);
        lq[i] = (uint32_t)__bfloat16_as_ushort(l0) | ((uint32_t)__bfloat16_as_ushort(l1) << 16);
    }
}
// pack two scale-folded fp32 weights into a hi- or lo-part bf16x2 word
__device__ __forceinline__ uint32_t packw(float w0, float w1, int hl) {
    __nv_bfloat16 h0 = __float2bfloat16(w0), h1 = __float2bfloat16(w1);
    unsigned short u0, u1;
    if (hl == 0) { u0 = __bfloat16_as_ushort(h0); u1 = __bfloat16_as_ushort(h1); }
    else {
        u0 = __bfloat16_as_ushort(__float2bfloat16(w0 - __bfloat162float(h0)));
        u1 = __bfloat16_as_ushort(__float2bfloat16(w1 - __bfloat162float(h1)));
    }
    return (uint32_t)u0 | ((uint32_t)u1 << 16);
}

// ---------------- qp = relu(conv1x1(res)+b), NCHW -> NHWC (1 px/thread, inline fold) ----------------
__global__ void __launch_bounds__(256) qp_kernel(const float* __restrict__ res,
                                                 const float* __restrict__ wv_w,
                                                 const float* __restrict__ wv_s,
                                                 const float* __restrict__ wv_b)
{
    __shared__ __align__(16) float sw[CDn*Cn];
    __shared__ float sb[Cn];
    for (int i = threadIdx.x; i < CDn*Cn; i += 256) {
        int co = i & 31, ci = i >> 5;
        sw[i] = wv_w[co*CDn + ci] * __ldg(&wv_s[co]);
    }
    if (threadIdx.x < Cn) sb[threadIdx.x] = wv_b[threadIdx.x];
    __syncthreads();
    int p0 = blockIdx.x * 256 + threadIdx.x;
    int b  = p0 >> 14;  int pix0 = p0 & 16383;
    const float* r0 = res + (size_t)b * CDn * HWn + pix0;

    float4 a0[8];
    #pragma unroll
    for (int j = 0; j < 8; j++) a0[j] = make_float4(0,0,0,0);

    #pragma unroll 4
    for (int ci = 0; ci < CDn; ci++) {
        float x0 = r0[(size_t)ci * HWn];
        const float4* wr = (const float4*)(sw + ci*Cn);
        #pragma unroll
        for (int j = 0; j < 8; j++) a0[j] = f4fma(x0, wr[j], a0[j]);
    }
    float4* o0 = (float4*)(g_qp + (size_t)p0 * Cn);
    #pragma unroll
    for (int j = 0; j < 8; j++) {
        float4 v0 = a0[j];
        v0.x = fmaxf(v0.x + sb[j*4+0], 0.f); v0.y = fmaxf(v0.y + sb[j*4+1], 0.f);
        v0.z = fmaxf(v0.z + sb[j*4+2], 0.f); v0.w = fmaxf(v0.w + sb[j*4+3], 0.f);
        o0[j] = v0;
    }
}

// ---------------- point attention: 4 threads/pixel, shfl-reduced dots ----------------
__global__ void __launch_bounds__(256) pa_kernel()
{
    int t   = blockIdx.x * 256 + threadIdx.x;
    int p   = t >> 2;
    int sub = t & 3;
    int b = p >> 14, pix = p & 16383, h = pix >> 7, w = pix & 127;

    const float4* qb = (const float4*)g_qp + (size_t)p * 8 + sub * 2;
    float4 q0 = qb[0], q1 = qb[1];

    float sc[25];
    #pragma unroll
    for (int k = 0; k < 25; k++) {
        int di = (k / 5) * 2 - 4, dj = (k % 5) * 2 - 4;
        int hh = h + di, ww = w + dj;
        float s = 0.f;
        if (k != 12 && hh >= 0 && hh < Hn && ww >= 0 && ww < Wn) {
            const float4* nb = (const float4*)g_qp + (size_t)((b << 14) + (hh << 7) + ww) * 8 + sub * 2;
            float4 v0 = nb[0], v1 = nb[1];
            s = q0.x*v0.x + q0.y*v0.y + q0.z*v0.z + q0.w*v0.w
              + q1.x*v1.x + q1.y*v1.y + q1.z*v1.z + q1.w*v1.w;
        }
        s += __shfl_xor_sync(0xFFFFFFFFu, s, 1);
        s += __shfl_xor_sync(0xFFFFFFFFu, s, 2);
        sc[k] = s;
    }
    float m = sc[0];
    #pragma unroll
    for (int k = 1; k < 25; k++) m = fmaxf(m, sc[k]);
    float Z = 0.f;
    #pragma unroll
    for (int k = 0; k < 25; k++) { sc[k] = __expf(sc[k] - m); Z += sc[k]; }
    float inv = 1.f / Z;

    float4 a0 = q0, a1 = q1;
    #pragma unroll
    for (int k = 0; k < 25; k++) {
        int di = (k / 5) * 2 - 4, dj = (k % 5) * 2 - 4;
        int hh = h + di, ww = w + dj;
        if (hh >= 0 && hh < Hn && ww >= 0 && ww < Wn) {
            float wgt = sc[k] * inv;
            const float4* nb = (const float4*)g_qp + (size_t)((b << 14) + (hh << 7) + ww) * 8 + sub * 2;
            a0 = f4fma(wgt, nb[0], a0);
            a1 = f4fma(wgt, nb[1], a1);
        }
    }
    float4* o = (float4*)(g_pc + (size_t)p * Cn) + sub * 2;
    o[0] = a0; o[1] = a1;
}

// ---------------- class attention + norm + residual -> xi (linear pixels) ----------------
__global__ void __launch_bounds__(256) ca_kernel(const float* __restrict__ attn,
                                                 const float* __restrict__ cn_s,
                                                 const float* __restrict__ cn_b)
{
    int p = blockIdx.x * 256 + threadIdx.x;
    int b = p >> 14, pix = p & 16383;
    float pcf[32];
    const float4* pc4 = (const float4*)g_pc + (size_t)p * 8;
    #pragma unroll
    for (int j = 0; j < 8; j++) {
        float4 v = pc4[j];
        pcf[j*4+0] = v.x; pcf[j*4+1] = v.y; pcf[j*4+2] = v.z; pcf[j*4+3] = v.w;
    }
    float s[8];
    #pragma unroll
    for (int n = 0; n < 8; n++) {
        const float* ap = attn + ((size_t)b * CDn + n * Cn) * HWn + pix;
        float acc = 0.f;
        #pragma unroll
        for (int c = 0; c < 32; c++) acc += pcf[c] * ap[(size_t)c * HWn];
        s[n] = acc;
    }
    float m = s[0];
    #pragma unroll
    for (int n = 1; n < 8; n++) m = fmaxf(m, s[n]);
    float Z = 0.f;
    #pragma unroll
    for (int n = 0; n < 8; n++) { s[n] = __expf(s[n] - m); Z += s[n]; }
    float inv = 1.f / Z;
    #pragma unroll
    for (int n = 0; n < 8; n++) {
        float wn = s[n] * inv;
        const float* ap = attn + ((size_t)b * CDn + n * Cn) * HWn + pix;
        float4* xo = (float4*)(g_xi + ((size_t)(b * NHn + n) * HWn + pix) * Cn);
        #pragma unroll
        for (int c4 = 0; c4 < 8; c4++) {
            float4 o; int c = c4 * 4;
            o.x = ap[(size_t)(c+0)*HWn] + wn * pcf[c+0] * __ldg(&cn_s[n*32+c+0]) + __ldg(&cn_b[n*32+c+0]);
            o.y = ap[(size_t)(c+1)*HWn] + wn * pcf[c+1] * __ldg(&cn_s[n*32+c+1]) + __ldg(&cn_b[n*32+c+1]);
            o.z = ap[(size_t)(c+2)*HWn] + wn * pcf[c+2] * __ldg(&cn_s[n*32+c+2]) + __ldg(&cn_b[n*32+c+2]);
            o.w = ap[(size_t)(c+3)*HWn] + wn * pcf[c+3] * __ldg(&cn_s[n*32+c+3]) + __ldg(&cn_b[n*32+c+3]);
            xo[c4] = o;
        }
    }
}

// ---------------- MSConv 3x3 stage via warp MMA (inline weight gen, batch-amortized) ----------------
template <int S>
__global__ void __launch_bounds__(256) conv_mma_kernel(const float* __restrict__ w3,
                                                       const float* __restrict__ s3,
                                                       const float* __restrict__ b3)
{
    constexpr int NBW = (S == 1) ? 3 : (S == 2) ? 2 : 1;
    constexpr int NB  = NBW * 4;
    constexpr int JB  = (S == 1) ? 0 : (S == 2) ? 3 : 5;
    constexpr int WCNT = 9 * NB * 256;
    constexpr int WBYTES = WCNT * 4;
    constexpr int INS  = (S == 1) ? 32 : 96;
    constexpr int CHOFF = (S == 3) ? 32 : 0;
    constexpr int OUTOFF = (S == 1) ? 0 : (S == 2) ? 32 : 64;

    extern __shared__ __align__(16) char smem[];
    const int tid = threadIdx.x;
    const int head = blockIdx.y;
    const int ty0 = (blockIdx.x >> 3) * 16, tx0 = (blockIdx.x & 7) * 16;

    // ---- generate fragment-ordered bf16 hi/lo weights inline (w3 is L2-resident) ----
    {
        uint32_t* wdst = (uint32_t*)(smem + 51840);
        for (int i = tid; i < WCNT; i += 256) {
            int r  = i & 1;
            int ln = (i >> 1) & 31;
            int hl = (i >> 6) & 1;
            int kb = (i >> 7) & 1;
            int tn = i >> 8;              // tap*NB + nb
            int nb = tn % NB, tap = tn / NB;
            int n  = nb * 8 + (ln >> 2);
            int j  = JB + (n >> 5);
            int oc = n & 31;
            int ci0 = kb * 16 + (ln & 3) * 2 + r * 8;
            int ky = tap / 3, kx = tap - 3 * (tap / 3);
            float s = __ldg(&s3[(head*6 + j)*32 + oc]);
            const float* wb = w3 + (((size_t)((head*6 + j)*32 + oc)*32 + ci0)*3 + ky)*3 + kx;
            wdst[i] = packw(__ldg(wb) * s, __ldg(wb + 9) * s, hl);
        }
        float* sb = (float*)(smem + 51840 + WBYTES);
        if (tid < NB * 8) sb[tid] = b3[(head*6 + JB + (tid >> 5))*32 + (tid & 31)];
    }

    const int lane = tid & 31, wid = tid >> 5;
    const int warpM = wid & 1, warpN = wid >> 1;
    const uint32_t koff = (lane & 16) ? 16u : 0u;
    const uint32_t abase = smem_u32(smem) + (uint32_t)(lane & 15) * 80 + koff;
    const uint2* wf = (const uint2*)(smem + 51840);
    const float* sbias = (const float*)(smem + 51840 + WBYTES);
    const int nl = (lane & 3) * 2;

    #pragma unroll 1
    for (int bb = 0; bb < Bn; bb++) {
        const int img = bb * NHn + head;
        {
            const float* gin = (S == 1) ? g_xi + (size_t)img * HWn * 32
                                        : g_cat + (size_t)img * HWn * 96;
            for (int e = tid; e < 324; e += 256) {
                int iy = e / 18, ix = e - iy * 18;
                int hh = ty0 - 1 + iy, ww = tx0 - 1 + ix;
                float x[32];
                if (hh >= 0 && hh < Hn && ww >= 0 && ww < Wn) {
                    const float4* p = (const float4*)(gin + (size_t)(hh * Wn + ww) * INS + CHOFF);
                    #pragma unroll
                    for (int q = 0; q < 8; q++) {
                        float4 v = p[q];
                        x[4*q] = v.x; x[4*q+1] = v.y; x[4*q+2] = v.z; x[4*q+3] = v.w;
                    }
                } else {
                    #pragma unroll
                    for (int i = 0; i < 32; i++) x[i] = 0.f;
                }
                uint32_t hq[16], lq[16];
                packhl(x, hq, lq, 16);
                uint4* rh = (uint4*)(smem + e * 80);
                uint4* rl = (uint4*)(smem + 25920 + e * 80);
                #pragma unroll
                for (int q = 0; q < 4; q++) {
                    rh[q] = make_uint4(hq[4*q], hq[4*q+1], hq[4*q+2], hq[4*q+3]);
                    rl[q] = make_uint4(lq[4*q], lq[4*q+1], lq[4*q+2], lq[4*q+3]);
                }
            }
        }
        __syncthreads();

        float acc[8][NBW][4];
        #pragma unroll
        for (int mb = 0; mb < 8; mb++)
            #pragma unroll
            for (int g = 0; g < NBW; g++)
                #pragma unroll
                for (int c = 0; c < 4; c++) acc[mb][g][c] = 0.f;

        #pragma unroll 1
        for (int tap = 0; tap < 9; tap++) {
            const int ky = tap / 3, kx = tap - ky * 3;
            uint32_t bh[NBW][4], bl[NBW][4];
            #pragma unroll
            for (int g = 0; g < NBW; g++) {
                int nb = warpN + g * 4;
                #pragma unroll
                for (int kb = 0; kb < 2; kb++) {
                    uint2 vh = wf[(size_t)((((tap * NB + nb) * 2 + kb) * 2 + 0) * 32 + lane)];
                    uint2 vl = wf[(size_t)((((tap * NB + nb) * 2 + kb) * 2 + 1) * 32 + lane)];
                    bh[g][2*kb] = vh.x; bh[g][2*kb+1] = vh.y;
                    bl[g][2*kb] = vl.x; bl[g][2*kb+1] = vl.y;
                }
            }
            const uint32_t rowbase = abase + (uint32_t)(((warpM * 8 + ky) * 18 + kx) * 80);
            #pragma unroll
            for (int mb = 0; mb < 8; mb++) {
                uint32_t ab = rowbase + (uint32_t)(mb * 18 * 80);
                uint32_t ah0[4], ah1[4], al0[4], al1[4];
                ldm4(ah0, ab);           ldm4(ah1, ab + 32);
                ldm4(al0, ab + 25920);   ldm4(al1, ab + 25920 + 32);
                #pragma unroll
                for (int g = 0; g < NBW; g++) {
                    mma4(acc[mb][g], ah0, bh[g][0], bh[g][1]);
                    mma4(acc[mb][g], ah1, bh[g][2], bh[g][3]);
                    mma4(acc[mb][g], al0, bh[g][0], bh[g][1]);
                    mma4(acc[mb][g], al1, bh[g][2], bh[g][3]);
                    mma4(acc[mb][g], ah0, bl[g][0], bl[g][1]);
                    mma4(acc[mb][g], ah1, bl[g][2], bl[g][3]);
                }
            }
        }

        #pragma unroll
        for (int mb = 0; mb < 8; mb++) {
            int py = ty0 + warpM * 8 + mb;
            float o[4];
            #pragma unroll
            for (int c = 0; c < 4; c++) {
                float s = 0.f;
                #pragma unroll
                for (int g = 0; g < NBW; g++) {
                    float b = sbias[(warpN + g * 4) * 8 + nl + (c & 1)];
                    s += fminf(fmaxf(acc[mb][g][c] + b, 0.f), 6.f);
                }
                o[c] = s;
            }
            int pxg = tx0 + (lane >> 2);
            int ch = OUTOFF + warpN * 8 + nl;
            float* p0 = g_cat + ((size_t)img * HWn + (size_t)py * Wn + pxg) * 96 + ch;
            *(float2*)p0 = make_float2(o[0], o[1]);
            *(float2*)(p0 + 8 * 96) = make_float2(o[2], o[3]);
        }
        __syncthreads();
    }
}

// ---------------- cat 1x1 (96->32) via warp MMA, inline weight gen, staged epilogue ----------------
// smem: Ah @0 (256 x 208B), Al @53248, Wf @106496 (12288 B), bias @118784; sD overlays @0 after sync.
__global__ void __launch_bounds__(256) final_mma_kernel(float* __restrict__ out,
                                                        const float* __restrict__ wcat,
                                                        const float* __restrict__ scat,
                                                        const float* __restrict__ bcat)
{
    extern __shared__ __align__(16) char smem[];
    const int tid = threadIdx.x;
    const int img = blockIdx.y, head = img & 7, blk = blockIdx.x;

    {
        uint32_t* wdst = (uint32_t*)(smem + 106496);
        for (int i = tid; i < 3072; i += 256) {
            int r  = i & 1;
            int ln = (i >> 1) & 31;
            int hl = (i >> 6) & 1;
            int kb = (i >> 7) % 6;
            int nb = (i >> 7) / 6;
            int n  = nb * 8 + (ln >> 2);
            int ci0 = kb * 16 + (ln & 3) * 2 + r * 8;
            float s = __ldg(&scat[head*32 + n]);
            const float* wb = wcat + (size_t)(head*32 + n) * 96 + ci0;
            wdst[i] = packw(__ldg(wb) * s, __ldg(wb + 1) * s, hl);
        }
        float* sb = (float*)(smem + 118784);
        if (tid < 32) sb[tid] = bcat[head * 32 + tid];
    }
    {
        const float* row = g_cat + ((size_t)img * HWn + blk * 256 + tid) * 96;
        #pragma unroll
        for (int q = 0; q < 6; q++) {
            float x[16];
            const float4* p4 = (const float4*)(row + q * 16);
            #pragma unroll
            for (int i = 0; i < 4; i++) {
                float4 v = p4[i];
                x[4*i] = v.x; x[4*i+1] = v.y; x[4*i+2] = v.z; x[4*i+3] = v.w;
            }
            uint32_t hq[8], lq[8];
            packhl(x, hq, lq, 8);
            uint4* rh = (uint4*)(smem + tid * 208 + q * 32);
            uint4* rl = (uint4*)(smem + 53248 + tid * 208 + q * 32);
            rh[0] = make_uint4(hq[0], hq[1], hq[2], hq[3]);
            rh[1] = make_uint4(hq[4], hq[5], hq[6], hq[7]);
            rl[0] = make_uint4(lq[0], lq[1], lq[2], lq[3]);
            rl[1] = make_uint4(lq[4], lq[5], lq[6], lq[7]);
        }
    }
    __syncthreads();

    const int lane = tid & 31, wid = tid >> 5;
    const uint32_t koff = (lane & 16) ? 16u : 0u;
    const uint32_t abase = smem_u32(smem) + (uint32_t)(lane & 15) * 208 + koff;
    const uint2* wf = (const uint2*)(smem + 106496);
    const float* sb = (const float*)(smem + 118784);

    float acc[2][4][4];
    #pragma unroll
    for (int m2 = 0; m2 < 2; m2++)
        #pragma unroll
        for (int nb = 0; nb < 4; nb++)
            #pragma unroll
            for (int c = 0; c < 4; c++) acc[m2][nb][c] = 0.f;

    #pragma unroll 1
    for (int kb = 0; kb < 6; kb++) {
        uint32_t ah[2][4], al[2][4];
        #pragma unroll
        for (int m2 = 0; m2 < 2; m2++) {
            uint32_t ab = abase + (uint32_t)((wid + m2 * 8) * 16 * 208 + kb * 32);
            ldm4(ah[m2], ab);
            ldm4(al[m2], ab + 53248);
        }
        #pragma unroll
        for (int nb = 0; nb < 4; nb++) {
            uint2 bhv = wf[((nb * 6 + kb) * 2 + 0) * 32 + lane];
            uint2 blv = wf[((nb * 6 + kb) * 2 + 1) * 32 + lane];
            #pragma unroll
            for (int m2 = 0; m2 < 2; m2++) {
                mma4(acc[m2][nb], ah[m2], bhv.x, bhv.y);
                mma4(acc[m2][nb], al[m2], bhv.x, bhv.y);
                mma4(acc[m2][nb], ah[m2], blv.x, blv.y);
            }
        }
    }
    __syncthreads();   // A region no longer needed; reuse as sD

    float* sD = (float*)smem;      // [32][258]
    const int nl = (lane & 3) * 2;
    #pragma unroll
    for (int m2 = 0; m2 < 2; m2++) {
        int mrow = (wid + m2 * 8) * 16;
        #pragma unroll
        for (int nb = 0; nb < 4; nb++) {
            int ch = nb * 8 + nl;
            #pragma unroll
            for (int cp = 0; cp < 2; cp++) {
                int pxl = mrow + (lane >> 2) + cp * 8;
                sD[ch * 258 + pxl]       = acc[m2][nb][2*cp];
                sD[(ch + 1) * 258 + pxl] = acc[m2][nb][2*cp + 1];
            }
        }
    }
    __syncthreads();

    const int p = blk * 256 + tid;
    const float4* xiv = (const float4*)(g_xi + ((size_t)img * HWn + p) * Cn);
    #pragma unroll
    for (int c4 = 0; c4 < 8; c4++) {
        float4 xr = xiv[c4];
        int c = c4 * 4;
        float o0 = fmaxf(sD[(c+0)*258 + tid] + sb[c+0] + xr.x, 0.f);
        float o1 = fmaxf(sD[(c+1)*258 + tid] + sb[c+1] + xr.y, 0.f);
        float o2 = fmaxf(sD[(c+2)*258 + tid] + sb[c+2] + xr.z, 0.f);
        float o3 = fmaxf(sD[(c+3)*258 + tid] + sb[c+3] + xr.w, 0.f);
        size_t base = (size_t)(img * 32 + c) * HWn + p;
        out[base]         = o0;
        out[base + HWn]   = o1;
        out[base + 2*HWn] = o2;
        out[base + 3*HWn] = o3;
    }
}

// ---------------- launch ----------------
extern "C" void kernel_launch(void* const* d_in, const int* in_sizes, int n_in,
                              void* d_out, int out_size)
{
    (void)in_sizes; (void)n_in; (void)out_size;
    const float* res  = (const float*)d_in[0];
    const float* attn = (const float*)d_in[1];
    const float* wv_w = (const float*)d_in[2];
    const float* wv_s = (const float*)d_in[3];
    const float* wv_b = (const float*)d_in[4];
    const float* cn_s = (const float*)d_in[5];
    const float* cn_b = (const float*)d_in[6];
    const float* w3   = (const float*)d_in[7];
    const float* s3   = (const float*)d_in[8];
    const float* b3   = (const float*)d_in[9];
    const float* wcat = (const float*)d_in[10];
    const float* scat = (const float*)d_in[11];
    const float* bcat = (const float*)d_in[12];
    float* out = (float*)d_out;

    const int SM1 = 51840 + 9*12*256*4 + 12*8*4;
    const int SM2 = 51840 + 9*8*256*4  + 8*8*4;
    const int SM3 = 51840 + 9*4*256*4  + 4*8*4;
    const int SMF = 118912;
    cudaFuncSetAttribute(conv_mma_kernel<1>, cudaFuncAttributeMaxDynamicSharedMemorySize, SM1);
    cudaFuncSetAttribute(conv_mma_kernel<2>, cudaFuncAttributeMaxDynamicSharedMemorySize, SM2);
    cudaFuncSetAttribute(conv_mma_kernel<3>, cudaFuncAttributeMaxDynamicSharedMemorySize, SM3);
    cudaFuncSetAttribute(final_mma_kernel, cudaFuncAttributeMaxDynamicSharedMemorySize, SMF);

    qp_kernel<<<256, 256>>>(res, wv_w, wv_s, wv_b);
    pa_kernel<<<1024, 256>>>();
    ca_kernel<<<256, 256>>>(attn, cn_s, cn_b);
    conv_mma_kernel<1><<<dim3(64, 8), 256, SM1>>>(w3, s3, b3);   // 4th launch -> profiled
    conv_mma_kernel<2><<<dim3(64, 8), 256, SM2>>>(w3, s3, b3);
    conv_mma_kernel<3><<<dim3(64, 8), 256, SM3>>>(w3, s3, b3);
    final_mma_kernel<<<dim3(64, 32), 256, SMF>>>(out, wcat, scat, bcat);
}

// round 16
// speedup vs baseline: 1.1931x; 1.1931x over previous
#include <cuda_runtime.h>
#include <cuda_bf16.h>
#include <cstdint>
#include <cstddef>

#define Bn  4
#define NHn 8
#define Cn  32
#define Hn  128
#define Wn  128
#define HWn (Hn*Wn)
#define CDn 256

// ---------------- scratch (device globals) ----------------
__device__ __align__(16) float g_qp [Bn*HWn*Cn];
__device__ __align__(16) float g_pc [Bn*HWn*Cn];
__device__ __align__(16) float g_xi [Bn*NHn*HWn*Cn];
__device__ __align__(16) float g_cat[(size_t)Bn*NHn*HWn*96];

__device__ __align__(16) float g_b1 [NHn*96];
__device__ __align__(16) float g_b2 [NHn*64];
__device__ __align__(16) float g_b3k[NHn*32];
__device__ __align__(16) float g_wc [NHn*96*32];
__device__ __align__(16) float g_bc [NHn*32];
__device__ __align__(16) float g_wv [CDn*Cn];
__device__ __align__(16) float g_wvb[Cn];

// mma B-fragment-ordered bf16 weights (packed ushort pairs in uint32)
__device__ __align__(16) uint32_t g_Wf1[NHn*9*12*2*2*64];
__device__ __align__(16) uint32_t g_Wf2[NHn*9* 8*2*2*64];
__device__ __align__(16) uint32_t g_Wf3[NHn*9* 4*2*2*64];
// cat 1x1 fragment weights
__device__ __align__(16) uint32_t g_Wfc[NHn*4*6*2*64];

// ---------------- helpers ----------------
__device__ __forceinline__ float4 f4fma(float a, float4 w, float4 acc) {
    acc.x = fmaf(a, w.x, acc.x); acc.y = fmaf(a, w.y, acc.y);
    acc.z = fmaf(a, w.z, acc.z); acc.w = fmaf(a, w.w, acc.w);
    return acc;
}
__device__ __forceinline__ uint32_t smem_u32(const void* p) {
    uint32_t a;
    asm("{ .reg .u64 t; cvta.to.shared.u64 t, %1; cvt.u32.u64 %0, t; }" : "=r"(a) : "l"(p));
    return a;
}
__device__ __forceinline__ void ldm4(uint32_t* r, uint32_t addr) {
    asm volatile("ldmatrix.sync.aligned.m8n8.x4.shared.b16 {%0,%1,%2,%3}, [%4];"
        : "=r"(r[0]), "=r"(r[1]), "=r"(r[2]), "=r"(r[3]) : "r"(addr));
}
__device__ __forceinline__ void mma4(float* d, const uint32_t* a, uint32_t b0, uint32_t b1) {
    asm volatile(
        "mma.sync.aligned.m16n8k16.row.col.f32.bf16.bf16.f32 "
        "{%0,%1,%2,%3}, {%4,%5,%6,%7}, {%8,%9}, {%0,%1,%2,%3};"
        : "+f"(d[0]), "+f"(d[1]), "+f"(d[2]), "+f"(d[3])
        : "r"(a[0]), "r"(a[1]), "r"(a[2]), "r"(a[3]), "r"(b0), "r"(b1));
}
__device__ __forceinline__ void packhl(const float* x, uint32_t* hq, uint32_t* lq, int n2) {
    #pragma unroll
    for (int i = 0; i < n2; i++) {
        __nv_bfloat16 h0 = __float2bfloat16(x[2*i]),   h1 = __float2bfloat16(x[2*i+1]);
        __nv_bfloat16 l0 = __float2bfloat16(x[2*i]   - __bfloat162float(h0));
        __nv_bfloat16 l1 = __float2bfloat16(x[2*i+1] - __bfloat162float(h1));
        hq[i] = (uint32_t)__bfloat16_as_ushort(h0) | ((uint32_t)__bfloat16_as_ushort(h1) << 16);
        lq[i] = (uint32_t)__bfloat16_as_ushort(l0) | ((uint32_t)__bfloat16_as_ushort(l1) << 16);
    }
}

// ---------------- prep: fold scales (1x1 weights, biases) ----------------
__global__ void prep_kernel(const float* __restrict__ wv_w, const float* __restrict__ wv_s,
                            const float* __restrict__ wv_b, const float* __restrict__ b3,
                            const float* __restrict__ wcat, const float* __restrict__ scat,
                            const float* __restrict__ bcat)
{
    int t = blockIdx.x * blockDim.x + threadIdx.x;
    const int NC = NHn*96*Cn, NV = CDn*Cn;
    if (t < NC) {
        int co = t & 31; int r = t >> 5; int ci = r % 96; int h = r / 96;
        g_wc[t] = wcat[(h*32 + co)*96 + ci] * scat[h*32 + co]; return;
    } t -= NC;
    if (t < NV) {
        int co = t & 31; int ci = t >> 5;
        g_wv[t] = wv_w[co*CDn + ci] * wv_s[co]; return;
    } t -= NV;
    if (t < NHn*96) {
        int co = t % 96; int h = t / 96; int j = co >> 5, oc = co & 31;
        g_b1[t] = b3[(h*6 + j)*32 + oc]; return;
    } t -= NHn*96;
    if (t < NHn*64) {
        int co = t % 64; int h = t / 64; int j = 3 + (co >> 5), oc = co & 31;
        g_b2[t] = b3[(h*6 + j)*32 + oc]; return;
    } t -= NHn*64;
    if (t < NHn*32) { int oc = t & 31; int h = t >> 5; g_b3k[t] = b3[(h*6 + 5)*32 + oc]; return; }
    t -= NHn*32;
    if (t < NHn*32) { g_bc[t] = bcat[t]; return; }
    t -= NHn*32;
    if (t < Cn) g_wvb[t] = wv_b[t];
}

// ---------------- prep: mma-fragment-ordered bf16 hi/lo conv weights ----------------
__global__ void prepB_kernel(const float* __restrict__ w3, const float* __restrict__ s3)
{
    const int C1 = NHn*9*12*256, C2 = NHn*9*8*256, C3 = NHn*9*4*256;
    int t = blockIdx.x * blockDim.x + threadIdx.x;
    uint32_t* dst; int NB, jb, idx;
    if (t < C1)              { dst = g_Wf1; NB = 12; jb = 0; idx = t; }
    else if ((t -= C1) < C2) { dst = g_Wf2; NB = 8;  jb = 3; idx = t; }
    else if ((t -= C2) < C3) { dst = g_Wf3; NB = 4;  jb = 5; idx = t; }
    else return;
    int r    = idx & 1;
    int lane = (idx >> 1) & 31;
    int hl   = (idx >> 6) & 1;
    int kb   = (idx >> 7) & 1;
    int nb   = (idx >> 8) % NB;
    int rest = (idx >> 8) / NB;
    int tap  = rest % 9;
    int h    = rest / 9;
    int n  = nb*8 + (lane >> 2);
    int j  = jb + (n >> 5);
    int oc = n & 31;
    int ci0 = kb*16 + (lane & 3)*2 + r*8;
    int ky = tap / 3, kx = tap % 3;
    float s = s3[(h*6 + j)*32 + oc];
    float w0 = w3[((((h*6 + j)*32 + oc)*32 + ci0    )*3 + ky)*3 + kx] * s;
    float w1 = w3[((((h*6 + j)*32 + oc)*32 + ci0 + 1)*3 + ky)*3 + kx] * s;
    __nv_bfloat16 h0 = __float2bfloat16(w0), h1 = __float2bfloat16(w1);
    unsigned short u0, u1;
    if (hl == 0) { u0 = __bfloat16_as_ushort(h0); u1 = __bfloat16_as_ushort(h1); }
    else {
        u0 = __bfloat16_as_ushort(__float2bfloat16(w0 - __bfloat162float(h0)));
        u1 = __bfloat16_as_ushort(__float2bfloat16(w1 - __bfloat162float(h1)));
    }
    dst[idx] = (uint32_t)u0 | ((uint32_t)u1 << 16);
}

// ---------------- prep: cat-1x1 fragment weights (reads scale-folded g_wc) ----------------
__global__ void prepC_kernel()
{
    int t = blockIdx.x * blockDim.x + threadIdx.x;
    if (t >= NHn*4*6*2*64) return;
    int r    = t & 1;
    int lane = (t >> 1) & 31;
    int hl   = (t >> 6) & 1;
    int rest = t >> 7;
    int kb   = rest % 6; rest /= 6;
    int nb   = rest % 4;
    int h    = rest / 4;
    int n   = nb*8 + (lane >> 2);
    int ci0 = kb*16 + (lane & 3)*2 + r*8;
    float w0 = g_wc[(h*96 + ci0    )*32 + n];
    float w1 = g_wc[(h*96 + ci0 + 1)*32 + n];
    __nv_bfloat16 h0 = __float2bfloat16(w0), h1 = __float2bfloat16(w1);
    unsigned short u0, u1;
    if (hl == 0) { u0 = __bfloat16_as_ushort(h0); u1 = __bfloat16_as_ushort(h1); }
    else {
        u0 = __bfloat16_as_ushort(__float2bfloat16(w0 - __bfloat162float(h0)));
        u1 = __bfloat16_as_ushort(__float2bfloat16(w1 - __bfloat162float(h1)));
    }
    g_Wfc[t] = (uint32_t)u0 | ((uint32_t)u1 << 16);
}

// ---------------- qp = relu(conv1x1(res)+b), NCHW -> NHWC (1 px/thread) ----------------
__global__ void __launch_bounds__(256) qp_kernel(const float* __restrict__ res)
{
    __shared__ __align__(16) float sw[CDn*Cn];
    __shared__ float sb[Cn];
    for (int i = threadIdx.x; i < CDn*Cn; i += 256) sw[i] = g_wv[i];
    if (threadIdx.x < Cn) sb[threadIdx.x] = g_wvb[threadIdx.x];
    __syncthreads();
    int p0 = blockIdx.x * 256 + threadIdx.x;
    int b  = p0 >> 14;  int pix0 = p0 & 16383;
    const float* r0 = res + (size_t)b * CDn * HWn + pix0;

    float4 a0[8];
    #pragma unroll
    for (int j = 0; j < 8; j++) a0[j] = make_float4(0,0,0,0);

    #pragma unroll 4
    for (int ci = 0; ci < CDn; ci++) {
        float x0 = r0[(size_t)ci * HWn];
        const float4* wr = (const float4*)(sw + ci*Cn);
        #pragma unroll
        for (int j = 0; j < 8; j++) a0[j] = f4fma(x0, wr[j], a0[j]);
    }
    float4* o0 = (float4*)(g_qp + (size_t)p0 * Cn);
    #pragma unroll
    for (int j = 0; j < 8; j++) {
        float4 v0 = a0[j];
        v0.x = fmaxf(v0.x + sb[j*4+0], 0.f); v0.y = fmaxf(v0.y + sb[j*4+1], 0.f);
        v0.z = fmaxf(v0.z + sb[j*4+2], 0.f); v0.w = fmaxf(v0.w + sb[j*4+3], 0.f);
        o0[j] = v0;
    }
}

// ---------------- point attention: 4 threads/pixel, shfl-reduced dots ----------------
__global__ void __launch_bounds__(256) pa_kernel()
{
    int t   = blockIdx.x * 256 + threadIdx.x;
    int p   = t >> 2;
    int sub = t & 3;
    int b = p >> 14, pix = p & 16383, h = pix >> 7, w = pix & 127;

    const float4* qb = (const float4*)g_qp + (size_t)p * 8 + sub * 2;
    float4 q0 = qb[0], q1 = qb[1];

    float sc[25];
    #pragma unroll
    for (int k = 0; k < 25; k++) {
        int di = (k / 5) * 2 - 4, dj = (k % 5) * 2 - 4;
        int hh = h + di, ww = w + dj;
        float s = 0.f;
        if (k != 12 && hh >= 0 && hh < Hn && ww >= 0 && ww < Wn) {
            const float4* nb = (const float4*)g_qp + (size_t)((b << 14) + (hh << 7) + ww) * 8 + sub * 2;
            float4 v0 = nb[0], v1 = nb[1];
            s = q0.x*v0.x + q0.y*v0.y + q0.z*v0.z + q0.w*v0.w
              + q1.x*v1.x + q1.y*v1.y + q1.z*v1.z + q1.w*v1.w;
        }
        s += __shfl_xor_sync(0xFFFFFFFFu, s, 1);
        s += __shfl_xor_sync(0xFFFFFFFFu, s, 2);
        sc[k] = s;
    }
    float m = sc[0];
    #pragma unroll
    for (int k = 1; k < 25; k++) m = fmaxf(m, sc[k]);
    float Z = 0.f;
    #pragma unroll
    for (int k = 0; k < 25; k++) { sc[k] = __expf(sc[k] - m); Z += sc[k]; }
    float inv = 1.f / Z;

    float4 a0 = q0, a1 = q1;
    #pragma unroll
    for (int k = 0; k < 25; k++) {
        int di = (k / 5) * 2 - 4, dj = (k % 5) * 2 - 4;
        int hh = h + di, ww = w + dj;
        if (hh >= 0 && hh < Hn && ww >= 0 && ww < Wn) {
            float wgt = sc[k] * inv;
            const float4* nb = (const float4*)g_qp + (size_t)((b << 14) + (hh << 7) + ww) * 8 + sub * 2;
            a0 = f4fma(wgt, nb[0], a0);
            a1 = f4fma(wgt, nb[1], a1);
        }
    }
    float4* o = (float4*)(g_pc + (size_t)p * Cn) + sub * 2;
    o[0] = a0; o[1] = a1;
}

// ---------------- class attention + norm + residual -> xi (linear pixels) ----------------
__global__ void __launch_bounds__(256) ca_kernel(const float* __restrict__ attn,
                                                 const float* __restrict__ cn_s,
                                                 const float* __restrict__ cn_b)
{
    int p = blockIdx.x * 256 + threadIdx.x;
    int b = p >> 14, pix = p & 16383;
    float pcf[32];
    const float4* pc4 = (const float4*)g_pc + (size_t)p * 8;
    #pragma unroll
    for (int j = 0; j < 8; j++) {
        float4 v = pc4[j];
        pcf[j*4+0] = v.x; pcf[j*4+1] = v.y; pcf[j*4+2] = v.z; pcf[j*4+3] = v.w;
    }
    float s[8];
    #pragma unroll
    for (int n = 0; n < 8; n++) {
        const float* ap = attn + ((size_t)b * CDn + n * Cn) * HWn + pix;
        float acc = 0.f;
        #pragma unroll
        for (int c = 0; c < 32; c++) acc += pcf[c] * ap[(size_t)c * HWn];
        s[n] = acc;
    }
    float m = s[0];
    #pragma unroll
    for (int n = 1; n < 8; n++) m = fmaxf(m, s[n]);
    float Z = 0.f;
    #pragma unroll
    for (int n = 0; n < 8; n++) { s[n] = __expf(s[n] - m); Z += s[n]; }
    float inv = 1.f / Z;
    #pragma unroll
    for (int n = 0; n < 8; n++) {
        float wn = s[n] * inv;
        const float* ap = attn + ((size_t)b * CDn + n * Cn) * HWn + pix;
        float4* xo = (float4*)(g_xi + ((size_t)(b * NHn + n) * HWn + pix) * Cn);
        #pragma unroll
        for (int c4 = 0; c4 < 8; c4++) {
            float4 o; int c = c4 * 4;
            o.x = ap[(size_t)(c+0)*HWn] + wn * pcf[c+0] * __ldg(&cn_s[n*32+c+0]) + __ldg(&cn_b[n*32+c+0]);
            o.y = ap[(size_t)(c+1)*HWn] + wn * pcf[c+1] * __ldg(&cn_s[n*32+c+1]) + __ldg(&cn_b[n*32+c+1]);
            o.z = ap[(size_t)(c+2)*HWn] + wn * pcf[c+2] * __ldg(&cn_s[n*32+c+2]) + __ldg(&cn_b[n*32+c+2]);
            o.w = ap[(size_t)(c+3)*HWn] + wn * pcf[c+3] * __ldg(&cn_s[n*32+c+3]) + __ldg(&cn_b[n*32+c+3]);
            xo[c4] = o;
        }
    }
}

// ---------------- MSConv 3x3 via warp MMA: A in smem only, weights streamed from L2 ----------------
// smem = A planes (51840 B) + bias -> 4 CTAs/SM
template <int S>
__global__ void __launch_bounds__(256) conv_mma_kernel()
{
    constexpr int NBW = (S == 1) ? 3 : (S == 2) ? 2 : 1;
    constexpr int NB  = NBW * 4;
    constexpr int WCNT = 9 * NB * 256;
    constexpr int INS  = (S == 1) ? 32 : 96;
    constexpr int CHOFF = (S == 3) ? 32 : 0;
    constexpr int OUTOFF = (S == 1) ? 0 : (S == 2) ? 32 : 64;

    extern __shared__ __align__(16) char smem[];
    const int tid = threadIdx.x;
    const int head = blockIdx.y;
    const int ty0 = (blockIdx.x >> 3) * 16, tx0 = (blockIdx.x & 7) * 16;

    float* sbias = (float*)(smem + 51840);
    {
        const float* gB = (S == 1) ? g_b1 : (S == 2) ? g_b2 : g_b3k;
        if (tid < NB * 8) sbias[tid] = gB[head * NB * 8 + tid];
    }
    const uint32_t* gWf = (S == 1) ? g_Wf1 : (S == 2) ? g_Wf2 : g_Wf3;
    const uint2* gw = (const uint2*)(gWf + (size_t)head * WCNT);

    const int lane = tid & 31, wid = tid >> 5;
    const int warpM = wid & 1, warpN = wid >> 1;
    const uint32_t koff = (lane & 16) ? 16u : 0u;
    const uint32_t abase = smem_u32(smem) + (uint32_t)(lane & 15) * 80 + koff;
    const int nl = (lane & 3) * 2;

    #pragma unroll 1
    for (int bb = 0; bb < Bn; bb++) {
        const int img = bb * NHn + head;
        {
            const float* gin = (S == 1) ? g_xi + (size_t)img * HWn * 32
                                        : g_cat + (size_t)img * HWn * 96;
            for (int e = tid; e < 324; e += 256) {
                int iy = e / 18, ix = e - iy * 18;
                int hh = ty0 - 1 + iy, ww = tx0 - 1 + ix;
                float x[32];
                if (hh >= 0 && hh < Hn && ww >= 0 && ww < Wn) {
                    const float4* p = (const float4*)(gin + (size_t)(hh * Wn + ww) * INS + CHOFF);
                    #pragma unroll
                    for (int q = 0; q < 8; q++) {
                        float4 v = p[q];
                        x[4*q] = v.x; x[4*q+1] = v.y; x[4*q+2] = v.z; x[4*q+3] = v.w;
                    }
                } else {
                    #pragma unroll
                    for (int i = 0; i < 32; i++) x[i] = 0.f;
                }
                uint32_t hq[16], lq[16];
                packhl(x, hq, lq, 16);
                uint4* rh = (uint4*)(smem + e * 80);
                uint4* rl = (uint4*)(smem + 25920 + e * 80);
                #pragma unroll
                for (int q = 0; q < 4; q++) {
                    rh[q] = make_uint4(hq[4*q], hq[4*q+1], hq[4*q+2], hq[4*q+3]);
                    rl[q] = make_uint4(lq[4*q], lq[4*q+1], lq[4*q+2], lq[4*q+3]);
                }
            }
        }
        __syncthreads();

        float acc[8][NBW][4];
        #pragma unroll
        for (int mb = 0; mb < 8; mb++)
            #pragma unroll
            for (int g = 0; g < NBW; g++)
                #pragma unroll
                for (int c = 0; c < 4; c++) acc[mb][g][c] = 0.f;

        #pragma unroll 1
        for (int tap = 0; tap < 9; tap++) {
            const int ky = tap / 3, kx = tap - ky * 3;
            uint32_t bh[NBW][4], bl[NBW][4];
            #pragma unroll
            for (int g = 0; g < NBW; g++) {
                int nb = warpN + g * 4;
                #pragma unroll
                for (int kb = 0; kb < 2; kb++) {
                    uint2 vh = __ldg(&gw[(size_t)((((tap * NB + nb) * 2 + kb) * 2 + 0) * 32 + lane)]);
                    uint2 vl = __ldg(&gw[(size_t)((((tap * NB + nb) * 2 + kb) * 2 + 1) * 32 + lane)]);
                    bh[g][2*kb] = vh.x; bh[g][2*kb+1] = vh.y;
                    bl[g][2*kb] = vl.x; bl[g][2*kb+1] = vl.y;
                }
            }
            const uint32_t rowbase = abase + (uint32_t)(((warpM * 8 + ky) * 18 + kx) * 80);
            #pragma unroll
            for (int mb = 0; mb < 8; mb++) {
                uint32_t ab = rowbase + (uint32_t)(mb * 18 * 80);
                uint32_t ah0[4], ah1[4], al0[4], al1[4];
                ldm4(ah0, ab);           ldm4(ah1, ab + 32);
                ldm4(al0, ab + 25920);   ldm4(al1, ab + 25920 + 32);
                #pragma unroll
                for (int g = 0; g < NBW; g++) {
                    mma4(acc[mb][g], ah0, bh[g][0], bh[g][1]);
                    mma4(acc[mb][g], ah1, bh[g][2], bh[g][3]);
                    mma4(acc[mb][g], al0, bh[g][0], bh[g][1]);
                    mma4(acc[mb][g], al1, bh[g][2], bh[g][3]);
                    mma4(acc[mb][g], ah0, bl[g][0], bl[g][1]);
                    mma4(acc[mb][g], ah1, bl[g][2], bl[g][3]);
                }
            }
        }

        #pragma unroll
        for (int mb = 0; mb < 8; mb++) {
            int py = ty0 + warpM * 8 + mb;
            float o[4];
            #pragma unroll
            for (int c = 0; c < 4; c++) {
                float s = 0.f;
                #pragma unroll
                for (int g = 0; g < NBW; g++) {
                    float b = sbias[(warpN + g * 4) * 8 + nl + (c & 1)];
                    s += fminf(fmaxf(acc[mb][g][c] + b, 0.f), 6.f);
                }
                o[c] = s;
            }
            int pxg = tx0 + (lane >> 2);
            int ch = OUTOFF + warpN * 8 + nl;
            float* p0 = g_cat + ((size_t)img * HWn + (size_t)py * Wn + pxg) * 96 + ch;
            *(float2*)p0 = make_float2(o[0], o[1]);
            *(float2*)(p0 + 8 * 96) = make_float2(o[2], o[3]);
        }
        __syncthreads();
    }
}

// ---------------- cat 1x1 (96->32) via warp MMA, smem-staged coalesced epilogue ----------------
__global__ void __launch_bounds__(256) final_mma_kernel(float* __restrict__ out)
{
    extern __shared__ __align__(16) char smem[];
    const int tid = threadIdx.x;
    const int img = blockIdx.y, head = img & 7, blk = blockIdx.x;

    {
        const uint4* wsrc = (const uint4*)(g_Wfc + (size_t)head * 3072);
        uint4* wdst = (uint4*)(smem + 106496);
        for (int i = tid; i < 768; i += 256) wdst[i] = wsrc[i];
        float* sb = (float*)(smem + 118784);
        if (tid < 32) sb[tid] = g_bc[head * 32 + tid];
    }
    {
        const float* row = g_cat + ((size_t)img * HWn + blk * 256 + tid) * 96;
        #pragma unroll
        for (int q = 0; q < 6; q++) {
            float x[16];
            const float4* p4 = (const float4*)(row + q * 16);
            #pragma unroll
            for (int i = 0; i < 4; i++) {
                float4 v = p4[i];
                x[4*i] = v.x; x[4*i+1] = v.y; x[4*i+2] = v.z; x[4*i+3] = v.w;
            }
            uint32_t hq[8], lq[8];
            packhl(x, hq, lq, 8);
            uint4* rh = (uint4*)(smem + tid * 208 + q * 32);
            uint4* rl = (uint4*)(smem + 53248 + tid * 208 + q * 32);
            rh[0] = make_uint4(hq[0], hq[1], hq[2], hq[3]);
            rh[1] = make_uint4(hq[4], hq[5], hq[6], hq[7]);
            rl[0] = make_uint4(lq[0], lq[1], lq[2], lq[3]);
            rl[1] = make_uint4(lq[4], lq[5], lq[6], lq[7]);
        }
    }
    __syncthreads();

    const int lane = tid & 31, wid = tid >> 5;
    const uint32_t koff = (lane & 16) ? 16u : 0u;
    const uint32_t abase = smem_u32(smem) + (uint32_t)(lane & 15) * 208 + koff;
    const uint2* wf = (const uint2*)(smem + 106496);
    const float* sb = (const float*)(smem + 118784);

    float acc[2][4][4];
    #pragma unroll
    for (int m2 = 0; m2 < 2; m2++)
        #pragma unroll
        for (int nb = 0; nb < 4; nb++)
            #pragma unroll
            for (int c = 0; c < 4; c++) acc[m2][nb][c] = 0.f;

    #pragma unroll 1
    for (int kb = 0; kb < 6; kb++) {
        uint32_t ah[2][4], al[2][4];
        #pragma unroll
        for (int m2 = 0; m2 < 2; m2++) {
            uint32_t ab = abase + (uint32_t)((wid + m2 * 8) * 16 * 208 + kb * 32);
            ldm4(ah[m2], ab);
            ldm4(al[m2], ab + 53248);
        }
        #pragma unroll
        for (int nb = 0; nb < 4; nb++) {
            uint2 bhv = wf[((nb * 6 + kb) * 2 + 0) * 32 + lane];
            uint2 blv = wf[((nb * 6 + kb) * 2 + 1) * 32 + lane];
            #pragma unroll
            for (int m2 = 0; m2 < 2; m2++) {
                mma4(acc[m2][nb], ah[m2], bhv.x, bhv.y);
                mma4(acc[m2][nb], al[m2], bhv.x, bhv.y);
                mma4(acc[m2][nb], ah[m2], blv.x, blv.y);
            }
        }
    }
    __syncthreads();   // A region no longer needed; reuse as sD

    float* sD = (float*)smem;      // [32][258]
    const int nl = (lane & 3) * 2;
    #pragma unroll
    for (int m2 = 0; m2 < 2; m2++) {
        int mrow = (wid + m2 * 8) * 16;
        #pragma unroll
        for (int nb = 0; nb < 4; nb++) {
            int ch = nb * 8 + nl;
            #pragma unroll
            for (int cp = 0; cp < 2; cp++) {
                int pxl = mrow + (lane >> 2) + cp * 8;
                sD[ch * 258 + pxl]       = acc[m2][nb][2*cp];
                sD[(ch + 1) * 258 + pxl] = acc[m2][nb][2*cp + 1];
            }
        }
    }
    __syncthreads();

    const int p = blk * 256 + tid;
    const float4* xiv = (const float4*)(g_xi + ((size_t)img * HWn + p) * Cn);
    #pragma unroll
    for (int c4 = 0; c4 < 8; c4++) {
        float4 xr = xiv[c4];
        int c = c4 * 4;
        float o0 = fmaxf(sD[(c+0)*258 + tid] + sb[c+0] + xr.x, 0.f);
        float o1 = fmaxf(sD[(c+1)*258 + tid] + sb[c+1] + xr.y, 0.f);
        float o2 = fmaxf(sD[(c+2)*258 + tid] + sb[c+2] + xr.z, 0.f);
        float o3 = fmaxf(sD[(c+3)*258 + tid] + sb[c+3] + xr.w, 0.f);
        size_t base = (size_t)(img * 32 + c) * HWn + p;
        out[base]         = o0;
        out[base + HWn]   = o1;
        out[base + 2*HWn] = o2;
        out[base + 3*HWn] = o3;
    }
}

// ---------------- launch ----------------
extern "C" void kernel_launch(void* const* d_in, const int* in_sizes, int n_in,
                              void* d_out, int out_size)
{
    (void)in_sizes; (void)n_in; (void)out_size;
    const float* res  = (const float*)d_in[0];
    const float* attn = (const float*)d_in[1];
    const float* wv_w = (const float*)d_in[2];
    const float* wv_s = (const float*)d_in[3];
    const float* wv_b = (const float*)d_in[4];
    const float* cn_s = (const float*)d_in[5];
    const float* cn_b = (const float*)d_in[6];
    const float* w3   = (const float*)d_in[7];
    const float* s3   = (const float*)d_in[8];
    const float* b3   = (const float*)d_in[9];
    const float* wcat = (const float*)d_in[10];
    const float* scat = (const float*)d_in[11];
    const float* bcat = (const float*)d_in[12];
    float* out = (float*)d_out;

    const int SMC = 51840 + 12*8*4;     // A planes + max bias (stage 1)
    const int SMF = 118912;
    cudaFuncSetAttribute(conv_mma_kernel<1>, cudaFuncAttributeMaxDynamicSharedMemorySize, SMC);
    cudaFuncSetAttribute(conv_mma_kernel<2>, cudaFuncAttributeMaxDynamicSharedMemorySize, SMC);
    cudaFuncSetAttribute(conv_mma_kernel<3>, cudaFuncAttributeMaxDynamicSharedMemorySize, SMC);
    cudaFuncSetAttribute(final_mma_kernel, cudaFuncAttributeMaxDynamicSharedMemorySize, SMF);

    prep_kernel<<<140, 256>>>(wv_w, wv_s, wv_b, b3, wcat, scat, bcat);
    prepB_kernel<<<1728, 256>>>(w3, s3);
    prepC_kernel<<<96, 256>>>();
    qp_kernel<<<256, 256>>>(res);
    pa_kernel<<<1024, 256>>>();
    ca_kernel<<<256, 256>>>(attn, cn_s, cn_b);
    conv_mma_kernel<1><<<dim3(64, 8), 256, SMC>>>();
    conv_mma_kernel<2><<<dim3(64, 8), 256, SMC>>>();
    conv_mma_kernel<3><<<dim3(64, 8), 256, SMC>>>();
    final_mma_kernel<<<dim3(64, 32), 256, SMF>>>(out);
}

// round 17
// speedup vs baseline: 1.2317x; 1.0324x over previous
#include <cuda_runtime.h>
#include <cuda_bf16.h>
#include <cstdint>
#include <cstddef>

#define Bn  4
#define NHn 8
#define Cn  32
#define Hn  128
#define Wn  128
#define HWn (Hn*Wn)
#define CDn 256

// ---------------- scratch (device globals) ----------------
__device__ __align__(16) float g_qp [Bn*HWn*Cn];
__device__ __align__(16) float g_pc [Bn*HWn*Cn];
__device__ __align__(16) float g_xi [Bn*NHn*HWn*Cn];
__device__ __align__(16) float g_cat[(size_t)Bn*NHn*HWn*96];

__device__ __align__(16) float g_b1 [NHn*96];
__device__ __align__(16) float g_b2 [NHn*64];
__device__ __align__(16) float g_b3k[NHn*32];
__device__ __align__(16) float g_wc [NHn*96*32];
__device__ __align__(16) float g_bc [NHn*32];
__device__ __align__(16) float g_wv [CDn*Cn];
__device__ __align__(16) float g_wvb[Cn];

// mma B-fragment-ordered bf16 weights (packed ushort pairs in uint32)
__device__ __align__(16) uint32_t g_Wf1[NHn*9*12*2*2*64];
__device__ __align__(16) uint32_t g_Wf2[NHn*9* 8*2*2*64];
__device__ __align__(16) uint32_t g_Wf3[NHn*9* 4*2*2*64];
// cat 1x1 fragment weights
__device__ __align__(16) uint32_t g_Wfc[NHn*4*6*2*64];

// ---------------- helpers ----------------
__device__ __forceinline__ float4 f4fma(float a, float4 w, float4 acc) {
    acc.x = fmaf(a, w.x, acc.x); acc.y = fmaf(a, w.y, acc.y);
    acc.z = fmaf(a, w.z, acc.z); acc.w = fmaf(a, w.w, acc.w);
    return acc;
}
__device__ __forceinline__ uint32_t smem_u32(const void* p) {
    uint32_t a;
    asm("{ .reg .u64 t; cvta.to.shared.u64 t, %1; cvt.u32.u64 %0, t; }" : "=r"(a) : "l"(p));
    return a;
}
__device__ __forceinline__ void ldm4(uint32_t* r, uint32_t addr) {
    asm volatile("ldmatrix.sync.aligned.m8n8.x4.shared.b16 {%0,%1,%2,%3}, [%4];"
        : "=r"(r[0]), "=r"(r[1]), "=r"(r[2]), "=r"(r[3]) : "r"(addr));
}
__device__ __forceinline__ void mma4(float* d, const uint32_t* a, uint32_t b0, uint32_t b1) {
    asm volatile(
        "mma.sync.aligned.m16n8k16.row.col.f32.bf16.bf16.f32 "
        "{%0,%1,%2,%3}, {%4,%5,%6,%7}, {%8,%9}, {%0,%1,%2,%3};"
        : "+f"(d[0]), "+f"(d[1]), "+f"(d[2]), "+f"(d[3])
        : "r"(a[0]), "r"(a[1]), "r"(a[2]), "r"(a[3]), "r"(b0), "r"(b1));
}
__device__ __forceinline__ void packhl(const float* x, uint32_t* hq, uint32_t* lq, int n2) {
    #pragma unroll
    for (int i = 0; i < n2; i++) {
        __nv_bfloat16 h0 = __float2bfloat16(x[2*i]),   h1 = __float2bfloat16(x[2*i+1]);
        __nv_bfloat16 l0 = __float2bfloat16(x[2*i]   - __bfloat162float(h0));
        __nv_bfloat16 l1 = __float2bfloat16(x[2*i+1] - __bfloat162float(h1));
        hq[i] = (uint32_t)__bfloat16_as_ushort(h0) | ((uint32_t)__bfloat16_as_ushort(h1) << 16);
        lq[i] = (uint32_t)__bfloat16_as_ushort(l0) | ((uint32_t)__bfloat16_as_ushort(l1) << 16);
    }
}

// ---------------- prep: fold scales (1x1 weights, biases) ----------------
__global__ void prep_kernel(const float* __restrict__ wv_w, const float* __restrict__ wv_s,
                            const float* __restrict__ wv_b, const float* __restrict__ b3,
                            const float* __restrict__ wcat, const float* __restrict__ scat,
                            const float* __restrict__ bcat)
{
    int t = blockIdx.x * blockDim.x + threadIdx.x;
    const int NC = NHn*96*Cn, NV = CDn*Cn;
    if (t < NC) {
        int co = t & 31; int r = t >> 5; int ci = r % 96; int h = r / 96;
        g_wc[t] = wcat[(h*32 + co)*96 + ci] * scat[h*32 + co]; return;
    } t -= NC;
    if (t < NV) {
        int co = t & 31; int ci = t >> 5;
        g_wv[t] = wv_w[co*CDn + ci] * wv_s[co]; return;
    } t -= NV;
    if (t < NHn*96) {
        int co = t % 96; int h = t / 96; int j = co >> 5, oc = co & 31;
        g_b1[t] = b3[(h*6 + j)*32 + oc]; return;
    } t -= NHn*96;
    if (t < NHn*64) {
        int co = t % 64; int h = t / 64; int j = 3 + (co >> 5), oc = co & 31;
        g_b2[t] = b3[(h*6 + j)*32 + oc]; return;
    } t -= NHn*64;
    if (t < NHn*32) { int oc = t & 31; int h = t >> 5; g_b3k[t] = b3[(h*6 + 5)*32 + oc]; return; }
    t -= NHn*32;
    if (t < NHn*32) { g_bc[t] = bcat[t]; return; }
    t -= NHn*32;
    if (t < Cn) g_wvb[t] = wv_b[t];
}

// ---------------- prep: mma-fragment-ordered bf16 hi/lo conv weights ----------------
__global__ void prepB_kernel(const float* __restrict__ w3, const float* __restrict__ s3)
{
    const int C1 = NHn*9*12*256, C2 = NHn*9*8*256, C3 = NHn*9*4*256;
    int t = blockIdx.x * blockDim.x + threadIdx.x;
    uint32_t* dst; int NB, jb, idx;
    if (t < C1)              { dst = g_Wf1; NB = 12; jb = 0; idx = t; }
    else if ((t -= C1) < C2) { dst = g_Wf2; NB = 8;  jb = 3; idx = t; }
    else if ((t -= C2) < C3) { dst = g_Wf3; NB = 4;  jb = 5; idx = t; }
    else return;
    int r    = idx & 1;
    int lane = (idx >> 1) & 31;
    int hl   = (idx >> 6) & 1;
    int kb   = (idx >> 7) & 1;
    int nb   = (idx >> 8) % NB;
    int rest = (idx >> 8) / NB;
    int tap  = rest % 9;
    int h    = rest / 9;
    int n  = nb*8 + (lane >> 2);
    int j  = jb + (n >> 5);
    int oc = n & 31;
    int ci0 = kb*16 + (lane & 3)*2 + r*8;
    int ky = tap / 3, kx = tap % 3;
    float s = s3[(h*6 + j)*32 + oc];
    float w0 = w3[((((h*6 + j)*32 + oc)*32 + ci0    )*3 + ky)*3 + kx] * s;
    float w1 = w3[((((h*6 + j)*32 + oc)*32 + ci0 + 1)*3 + ky)*3 + kx] * s;
    __nv_bfloat16 h0 = __float2bfloat16(w0), h1 = __float2bfloat16(w1);
    unsigned short u0, u1;
    if (hl == 0) { u0 = __bfloat16_as_ushort(h0); u1 = __bfloat16_as_ushort(h1); }
    else {
        u0 = __bfloat16_as_ushort(__float2bfloat16(w0 - __bfloat162float(h0)));
        u1 = __bfloat16_as_ushort(__float2bfloat16(w1 - __bfloat162float(h1)));
    }
    dst[idx] = (uint32_t)u0 | ((uint32_t)u1 << 16);
}

// ---------------- prep: cat-1x1 fragment weights (reads scale-folded g_wc) ----------------
__global__ void prepC_kernel()
{
    int t = blockIdx.x * blockDim.x + threadIdx.x;
    if (t >= NHn*4*6*2*64) return;
    int r    = t & 1;
    int lane = (t >> 1) & 31;
    int hl   = (t >> 6) & 1;
    int rest = t >> 7;
    int kb   = rest % 6; rest /= 6;
    int nb   = rest % 4;
    int h    = rest / 4;
    int n   = nb*8 + (lane >> 2);
    int ci0 = kb*16 + (lane & 3)*2 + r*8;
    float w0 = g_wc[(h*96 + ci0    )*32 + n];
    float w1 = g_wc[(h*96 + ci0 + 1)*32 + n];
    __nv_bfloat16 h0 = __float2bfloat16(w0), h1 = __float2bfloat16(w1);
    unsigned short u0, u1;
    if (hl == 0) { u0 = __bfloat16_as_ushort(h0); u1 = __bfloat16_as_ushort(h1); }
    else {
        u0 = __bfloat16_as_ushort(__float2bfloat16(w0 - __bfloat162float(h0)));
        u1 = __bfloat16_as_ushort(__float2bfloat16(w1 - __bfloat162float(h1)));
    }
    g_Wfc[t] = (uint32_t)u0 | ((uint32_t)u1 << 16);
}

// ---------------- qp = relu(conv1x1(res)+b), NCHW -> NHWC (1 px/thread) ----------------
__global__ void __launch_bounds__(256) qp_kernel(const float* __restrict__ res)
{
    __shared__ __align__(16) float sw[CDn*Cn];
    __shared__ float sb[Cn];
    for (int i = threadIdx.x; i < CDn*Cn; i += 256) sw[i] = g_wv[i];
    if (threadIdx.x < Cn) sb[threadIdx.x] = g_wvb[threadIdx.x];
    __syncthreads();
    int p0 = blockIdx.x * 256 + threadIdx.x;
    int b  = p0 >> 14;  int pix0 = p0 & 16383;
    const float* r0 = res + (size_t)b * CDn * HWn + pix0;

    float4 a0[8];
    #pragma unroll
    for (int j = 0; j < 8; j++) a0[j] = make_float4(0,0,0,0);

    #pragma unroll 4
    for (int ci = 0; ci < CDn; ci++) {
        float x0 = r0[(size_t)ci * HWn];
        const float4* wr = (const float4*)(sw + ci*Cn);
        #pragma unroll
        for (int j = 0; j < 8; j++) a0[j] = f4fma(x0, wr[j], a0[j]);
    }
    float4* o0 = (float4*)(g_qp + (size_t)p0 * Cn);
    #pragma unroll
    for (int j = 0; j < 8; j++) {
        float4 v0 = a0[j];
        v0.x = fmaxf(v0.x + sb[j*4+0], 0.f); v0.y = fmaxf(v0.y + sb[j*4+1], 0.f);
        v0.z = fmaxf(v0.z + sb[j*4+2], 0.f); v0.w = fmaxf(v0.w + sb[j*4+3], 0.f);
        o0[j] = v0;
    }
}

// ---------------- point attention: 4 threads/pixel, shfl-reduced dots ----------------
__global__ void __launch_bounds__(256) pa_kernel()
{
    int t   = blockIdx.x * 256 + threadIdx.x;
    int p   = t >> 2;
    int sub = t & 3;
    int b = p >> 14, pix = p & 16383, h = pix >> 7, w = pix & 127;

    const float4* qb = (const float4*)g_qp + (size_t)p * 8 + sub * 2;
    float4 q0 = qb[0], q1 = qb[1];

    float sc[25];
    #pragma unroll
    for (int k = 0; k < 25; k++) {
        int di = (k / 5) * 2 - 4, dj = (k % 5) * 2 - 4;
        int hh = h + di, ww = w + dj;
        float s = 0.f;
        if (k != 12 && hh >= 0 && hh < Hn && ww >= 0 && ww < Wn) {
            const float4* nb = (const float4*)g_qp + (size_t)((b << 14) + (hh << 7) + ww) * 8 + sub * 2;
            float4 v0 = nb[0], v1 = nb[1];
            s = q0.x*v0.x + q0.y*v0.y + q0.z*v0.z + q0.w*v0.w
              + q1.x*v1.x + q1.y*v1.y + q1.z*v1.z + q1.w*v1.w;
        }
        s += __shfl_xor_sync(0xFFFFFFFFu, s, 1);
        s += __shfl_xor_sync(0xFFFFFFFFu, s, 2);
        sc[k] = s;
    }
    float m = sc[0];
    #pragma unroll
    for (int k = 1; k < 25; k++) m = fmaxf(m, sc[k]);
    float Z = 0.f;
    #pragma unroll
    for (int k = 0; k < 25; k++) { sc[k] = __expf(sc[k] - m); Z += sc[k]; }
    float inv = 1.f / Z;

    float4 a0 = q0, a1 = q1;
    #pragma unroll
    for (int k = 0; k < 25; k++) {
        int di = (k / 5) * 2 - 4, dj = (k % 5) * 2 - 4;
        int hh = h + di, ww = w + dj;
        if (hh >= 0 && hh < Hn && ww >= 0 && ww < Wn) {
            float wgt = sc[k] * inv;
            const float4* nb = (const float4*)g_qp + (size_t)((b << 14) + (hh << 7) + ww) * 8 + sub * 2;
            a0 = f4fma(wgt, nb[0], a0);
            a1 = f4fma(wgt, nb[1], a1);
        }
    }
    float4* o = (float4*)(g_pc + (size_t)p * Cn) + sub * 2;
    o[0] = a0; o[1] = a1;
}

// ---------------- class attention: 4 threads/pixel, attn cached in registers ----------------
__global__ void __launch_bounds__(256) ca_kernel(const float* __restrict__ attn,
                                                 const float* __restrict__ cn_s,
                                                 const float* __restrict__ cn_b)
{
    int t   = blockIdx.x * 256 + threadIdx.x;
    int p   = t >> 2;
    int sub = t & 3;
    int b = p >> 14, pix = p & 16383;

    const float4* pc4 = (const float4*)g_pc + (size_t)p * 8 + sub * 2;
    float4 pq0 = pc4[0], pq1 = pc4[1];
    float pcf[8] = { pq0.x, pq0.y, pq0.z, pq0.w, pq1.x, pq1.y, pq1.z, pq1.w };

    float apv[8][8];
    float s[8];
    #pragma unroll
    for (int n = 0; n < 8; n++) {
        const float* ap = attn + ((size_t)b * CDn + n * Cn + sub * 8) * HWn + pix;
        float acc = 0.f;
        #pragma unroll
        for (int i = 0; i < 8; i++) {
            float v = ap[(size_t)i * HWn];
            apv[n][i] = v;
            acc += pcf[i] * v;
        }
        acc += __shfl_xor_sync(0xFFFFFFFFu, acc, 1);
        acc += __shfl_xor_sync(0xFFFFFFFFu, acc, 2);
        s[n] = acc;
    }
    float m = s[0];
    #pragma unroll
    for (int n = 1; n < 8; n++) m = fmaxf(m, s[n]);
    float Z = 0.f;
    #pragma unroll
    for (int n = 0; n < 8; n++) { s[n] = __expf(s[n] - m); Z += s[n]; }
    float inv = 1.f / Z;

    #pragma unroll
    for (int n = 0; n < 8; n++) {
        float wn = s[n] * inv;
        float o[8];
        #pragma unroll
        for (int i = 0; i < 8; i++) {
            int c = sub * 8 + i;
            o[i] = apv[n][i] + wn * pcf[i] * __ldg(&cn_s[n*32 + c]) + __ldg(&cn_b[n*32 + c]);
        }
        float4* xo = (float4*)(g_xi + ((size_t)(b * NHn + n) * HWn + pix) * Cn + sub * 8);
        xo[0] = make_float4(o[0], o[1], o[2], o[3]);
        xo[1] = make_float4(o[4], o[5], o[6], o[7]);
    }
}

// ---------------- MSConv 3x3 via warp MMA: A in smem, weights streamed, 2 CTAs/SM ----------------
template <int S>
__global__ void __launch_bounds__(256, 2) conv_mma_kernel()
{
    constexpr int NBW = (S == 1) ? 3 : (S == 2) ? 2 : 1;
    constexpr int NB  = NBW * 4;
    constexpr int WCNT = 9 * NB * 256;
    constexpr int INS  = (S == 1) ? 32 : 96;
    constexpr int CHOFF = (S == 3) ? 32 : 0;
    constexpr int OUTOFF = (S == 1) ? 0 : (S == 2) ? 32 : 64;

    extern __shared__ __align__(16) char smem[];
    const int tid = threadIdx.x;
    const int head = blockIdx.y;
    const int ty0 = (blockIdx.x >> 3) * 16, tx0 = (blockIdx.x & 7) * 16;

    float* sbias = (float*)(smem + 51840);
    {
        const float* gB = (S == 1) ? g_b1 : (S == 2) ? g_b2 : g_b3k;
        if (tid < NB * 8) sbias[tid] = gB[head * NB * 8 + tid];
    }
    const uint32_t* gWf = (S == 1) ? g_Wf1 : (S == 2) ? g_Wf2 : g_Wf3;
    const uint2* gw = (const uint2*)(gWf + (size_t)head * WCNT);

    const int lane = tid & 31, wid = tid >> 5;
    const int warpM = wid & 1, warpN = wid >> 1;
    const uint32_t koff = (lane & 16) ? 16u : 0u;
    const uint32_t abase = smem_u32(smem) + (uint32_t)(lane & 15) * 80 + koff;
    const int nl = (lane & 3) * 2;

    #pragma unroll 1
    for (int bb = 0; bb < Bn; bb++) {
        const int img = bb * NHn + head;
        {
            const float* gin = (S == 1) ? g_xi + (size_t)img * HWn * 32
                                        : g_cat + (size_t)img * HWn * 96;
            for (int e = tid; e < 324; e += 256) {
                int iy = e / 18, ix = e - iy * 18;
                int hh = ty0 - 1 + iy, ww = tx0 - 1 + ix;
                float x[32];
                if (hh >= 0 && hh < Hn && ww >= 0 && ww < Wn) {
                    const float4* p = (const float4*)(gin + (size_t)(hh * Wn + ww) * INS + CHOFF);
                    #pragma unroll
                    for (int q = 0; q < 8; q++) {
                        float4 v = p[q];
                        x[4*q] = v.x; x[4*q+1] = v.y; x[4*q+2] = v.z; x[4*q+3] = v.w;
                    }
                } else {
                    #pragma unroll
                    for (int i = 0; i < 32; i++) x[i] = 0.f;
                }
                uint32_t hq[16], lq[16];
                packhl(x, hq, lq, 16);
                uint4* rh = (uint4*)(smem + e * 80);
                uint4* rl = (uint4*)(smem + 25920 + e * 80);
                #pragma unroll
                for (int q = 0; q < 4; q++) {
                    rh[q] = make_uint4(hq[4*q], hq[4*q+1], hq[4*q+2], hq[4*q+3]);
                    rl[q] = make_uint4(lq[4*q], lq[4*q+1], lq[4*q+2], lq[4*q+3]);
                }
            }
        }
        __syncthreads();

        float acc[8][NBW][4];
        #pragma unroll
        for (int mb = 0; mb < 8; mb++)
            #pragma unroll
            for (int g = 0; g < NBW; g++)
                #pragma unroll
                for (int c = 0; c < 4; c++) acc[mb][g][c] = 0.f;

        #pragma unroll 1
        for (int tap = 0; tap < 9; tap++) {
            const int ky = tap / 3, kx = tap - ky * 3;
            uint32_t bh[NBW][4], bl[NBW][4];
            #pragma unroll
            for (int g = 0; g < NBW; g++) {
                int nb = warpN + g * 4;
                #pragma unroll
                for (int kb = 0; kb < 2; kb++) {
                    uint2 vh = __ldg(&gw[(size_t)((((tap * NB + nb) * 2 + kb) * 2 + 0) * 32 + lane)]);
                    uint2 vl = __ldg(&gw[(size_t)((((tap * NB + nb) * 2 + kb) * 2 + 1) * 32 + lane)]);
                    bh[g][2*kb] = vh.x; bh[g][2*kb+1] = vh.y;
                    bl[g][2*kb] = vl.x; bl[g][2*kb+1] = vl.y;
                }
            }
            const uint32_t rowbase = abase + (uint32_t)(((warpM * 8 + ky) * 18 + kx) * 80);
            #pragma unroll
            for (int mb = 0; mb < 8; mb++) {
                uint32_t ab = rowbase + (uint32_t)(mb * 18 * 80);
                uint32_t ah0[4], ah1[4], al0[4], al1[4];
                ldm4(ah0, ab);           ldm4(ah1, ab + 32);
                ldm4(al0, ab + 25920);   ldm4(al1, ab + 25920 + 32);
                #pragma unroll
                for (int g = 0; g < NBW; g++) {
                    mma4(acc[mb][g], ah0, bh[g][0], bh[g][1]);
                    mma4(acc[mb][g], ah1, bh[g][2], bh[g][3]);
                    mma4(acc[mb][g], al0, bh[g][0], bh[g][1]);
                    mma4(acc[mb][g], al1, bh[g][2], bh[g][3]);
                    mma4(acc[mb][g], ah0, bl[g][0], bl[g][1]);
                    mma4(acc[mb][g], ah1, bl[g][2], bl[g][3]);
                }
            }
        }

        #pragma unroll
        for (int mb = 0; mb < 8; mb++) {
            int py = ty0 + warpM * 8 + mb;
            float o[4];
            #pragma unroll
            for (int c = 0; c < 4; c++) {
                float s = 0.f;
                #pragma unroll
                for (int g = 0; g < NBW; g++) {
                    float b = sbias[(warpN + g * 4) * 8 + nl + (c & 1)];
                    s += fminf(fmaxf(acc[mb][g][c] + b, 0.f), 6.f);
                }
                o[c] = s;
            }
            int pxg = tx0 + (lane >> 2);
            int ch = OUTOFF + warpN * 8 + nl;
            float* p0 = g_cat + ((size_t)img * HWn + (size_t)py * Wn + pxg) * 96 + ch;
            *(float2*)p0 = make_float2(o[0], o[1]);
            *(float2*)(p0 + 8 * 96) = make_float2(o[2], o[3]);
        }
        __syncthreads();
    }
}

// ---------------- cat 1x1 (96->32) via warp MMA, smem-staged coalesced epilogue ----------------
__global__ void __launch_bounds__(256) final_mma_kernel(float* __restrict__ out)
{
    extern __shared__ __align__(16) char smem[];
    const int tid = threadIdx.x;
    const int img = blockIdx.y, head = img & 7, blk = blockIdx.x;

    {
        const uint4* wsrc = (const uint4*)(g_Wfc + (size_t)head * 3072);
        uint4* wdst = (uint4*)(smem + 106496);
        for (int i = tid; i < 768; i += 256) wdst[i] = wsrc[i];
        float* sb = (float*)(smem + 118784);
        if (tid < 32) sb[tid] = g_bc[head * 32 + tid];
    }
    {
        const float* row = g_cat + ((size_t)img * HWn + blk * 256 + tid) * 96;
        #pragma unroll
        for (int q = 0; q < 6; q++) {
            float x[16];
            const float4* p4 = (const float4*)(row + q * 16);
            #pragma unroll
            for (int i = 0; i < 4; i++) {
                float4 v = p4[i];
                x[4*i] = v.x; x[4*i+1] = v.y; x[4*i+2] = v.z; x[4*i+3] = v.w;
            }
            uint32_t hq[8], lq[8];
            packhl(x, hq, lq, 8);
            uint4* rh = (uint4*)(smem + tid * 208 + q * 32);
            uint4* rl = (uint4*)(smem + 53248 + tid * 208 + q * 32);
            rh[0] = make_uint4(hq[0], hq[1], hq[2], hq[3]);
            rh[1] = make_uint4(hq[4], hq[5], hq[6], hq[7]);
            rl[0] = make_uint4(lq[0], lq[1], lq[2], lq[3]);
            rl[1] = make_uint4(lq[4], lq[5], lq[6], lq[7]);
        }
    }
    __syncthreads();

    const int lane = tid & 31, wid = tid >> 5;
    const uint32_t koff = (lane & 16) ? 16u : 0u;
    const uint32_t abase = smem_u32(smem) + (uint32_t)(lane & 15) * 208 + koff;
    const uint2* wf = (const uint2*)(smem + 106496);
    const float* sb = (const float*)(smem + 118784);

    float acc[2][4][4];
    #pragma unroll
    for (int m2 = 0; m2 < 2; m2++)
        #pragma unroll
        for (int nb = 0; nb < 4; nb++)
            #pragma unroll
            for (int c = 0; c < 4; c++) acc[m2][nb][c] = 0.f;

    #pragma unroll 1
    for (int kb = 0; kb < 6; kb++) {
        uint32_t ah[2][4], al[2][4];
        #pragma unroll
        for (int m2 = 0; m2 < 2; m2++) {
            uint32_t ab = abase + (uint32_t)((wid + m2 * 8) * 16 * 208 + kb * 32);
            ldm4(ah[m2], ab);
            ldm4(al[m2], ab + 53248);
        }
        #pragma unroll
        for (int nb = 0; nb < 4; nb++) {
            uint2 bhv = wf[((nb * 6 + kb) * 2 + 0) * 32 + lane];
            uint2 blv = wf[((nb * 6 + kb) * 2 + 1) * 32 + lane];
            #pragma unroll
            for (int m2 = 0; m2 < 2; m2++) {
                mma4(acc[m2][nb], ah[m2], bhv.x, bhv.y);
                mma4(acc[m2][nb], al[m2], bhv.x, bhv.y);
                mma4(acc[m2][nb], ah[m2], blv.x, blv.y);
            }
        }
    }
    __syncthreads();   // A region no longer needed; reuse as sD

    float* sD = (float*)smem;      // [32][258]
    const int nl = (lane & 3) * 2;
    #pragma unroll
    for (int m2 = 0; m2 < 2; m2++) {
        int mrow = (wid + m2 * 8) * 16;
        #pragma unroll
        for (int nb = 0; nb < 4; nb++) {
            int ch = nb * 8 + nl;
            #pragma unroll
            for (int cp = 0; cp < 2; cp++) {
                int pxl = mrow + (lane >> 2) + cp * 8;
                sD[ch * 258 + pxl]       = acc[m2][nb][2*cp];
                sD[(ch + 1) * 258 + pxl] = acc[m2][nb][2*cp + 1];
            }
        }
    }
    __syncthreads();

    const int p = blk * 256 + tid;
    const float4* xiv = (const float4*)(g_xi + ((size_t)img * HWn + p) * Cn);
    #pragma unroll
    for (int c4 = 0; c4 < 8; c4++) {
        float4 xr = xiv[c4];
        int c = c4 * 4;
        float o0 = fmaxf(sD[(c+0)*258 + tid] + sb[c+0] + xr.x, 0.f);
        float o1 = fmaxf(sD[(c+1)*258 + tid] + sb[c+1] + xr.y, 0.f);
        float o2 = fmaxf(sD[(c+2)*258 + tid] + sb[c+2] + xr.z, 0.f);
        float o3 = fmaxf(sD[(c+3)*258 + tid] + sb[c+3] + xr.w, 0.f);
        size_t base = (size_t)(img * 32 + c) * HWn + p;
        out[base]         = o0;
        out[base + HWn]   = o1;
        out[base + 2*HWn] = o2;
        out[base + 3*HWn] = o3;
    }
}

// ---------------- launch ----------------
extern "C" void kernel_launch(void* const* d_in, const int* in_sizes, int n_in,
                              void* d_out, int out_size)
{
    (void)in_sizes; (void)n_in; (void)out_size;
    const float* res  = (const float*)d_in[0];
    const float* attn = (const float*)d_in[1];
    const float* wv_w = (const float*)d_in[2];
    const float* wv_s = (const float*)d_in[3];
    const float* wv_b = (const float*)d_in[4];
    const float* cn_s = (const float*)d_in[5];
    const float* cn_b = (const float*)d_in[6];
    const float* w3   = (const float*)d_in[7];
    const float* s3   = (const float*)d_in[8];
    const float* b3   = (const float*)d_in[9];
    const float* wcat = (const float*)d_in[10];
    const float* scat = (const float*)d_in[11];
    const float* bcat = (const float*)d_in[12];
    float* out = (float*)d_out;

    const int SMC = 51840 + 12*8*4;     // A planes + max bias (stage 1)
    const int SMF = 118912;
    cudaFuncSetAttribute(conv_mma_kernel<1>, cudaFuncAttributeMaxDynamicSharedMemorySize, SMC);
    cudaFuncSetAttribute(conv_mma_kernel<2>, cudaFuncAttributeMaxDynamicSharedMemorySize, SMC);
    cudaFuncSetAttribute(conv_mma_kernel<3>, cudaFuncAttributeMaxDynamicSharedMemorySize, SMC);
    cudaFuncSetAttribute(final_mma_kernel, cudaFuncAttributeMaxDynamicSharedMemorySize, SMF);

    prep_kernel<<<140, 256>>>(wv_w, wv_s, wv_b, b3, wcat, scat, bcat);
    prepB_kernel<<<1728, 256>>>(w3, s3);
    prepC_kernel<<<96, 256>>>();
    qp_kernel<<<256, 256>>>(res);
    pa_kernel<<<1024, 256>>>();
    ca_kernel<<<1024, 256>>>(attn, cn_s, cn_b);
    conv_mma_kernel<1><<<dim3(64, 8), 256, SMC>>>();
    conv_mma_kernel<2><<<dim3(64, 8), 256, SMC>>>();
    conv_mma_kernel<3><<<dim3(64, 8), 256, SMC>>>();
    final_mma_kernel<<<dim3(64, 32), 256, SMF>>>(out);
}